// round 13
// baseline (speedup 1.0000x reference)
#include <cuda_runtime.h>
#include <cuda_bf16.h>
#include <math.h>

#define T 4096
#define C 256
#define B 4

// Scratch (allocation-free rule: __device__ globals)
__device__ __nv_bfloat16 g_normed_t[B * T * C];      // [b][t][c] bf16
__device__ __nv_bfloat16 g_qkv[B * 3 * C * T];       // [b][768][t] bf16, q pre-scaled
__device__ __nv_bfloat16 g_ht[B * T * C];            // [b][t][c] bf16
__device__ __nv_bfloat16 g_wq[768 * 256];            // qkv_w bf16
__device__ __nv_bfloat16 g_wp[256 * 256];            // proj_w bf16
__device__ float g_part[64][8][2];

#define SCALE_Q 0.18033688f   // 0.125 * log2(e)
#define ONES_BF16X2 0x3F803F80u

// ---------------------------------------------------------------------------
// helpers
// ---------------------------------------------------------------------------
__device__ __forceinline__ unsigned pack_bf16(float a, float b) {
    __nv_bfloat162 h = __floats2bfloat162_rn(a, b);
    return *reinterpret_cast<unsigned*>(&h);
}
__device__ __forceinline__ unsigned ex2_bf16x2(unsigned x) {
    unsigned r;
    asm("ex2.approx.ftz.bf16x2 %0, %1;" : "=r"(r) : "r"(x));
    return r;
}
__device__ __forceinline__ void mma_bf16(float* d, const unsigned* a,
                                         unsigned b0, unsigned b1) {
    asm volatile(
        "mma.sync.aligned.m16n8k16.row.col.f32.bf16.bf16.f32 "
        "{%0,%1,%2,%3}, {%4,%5,%6,%7}, {%8,%9}, {%0,%1,%2,%3};"
        : "+f"(d[0]), "+f"(d[1]), "+f"(d[2]), "+f"(d[3])
        : "r"(a[0]), "r"(a[1]), "r"(a[2]), "r"(a[3]), "r"(b0), "r"(b1));
}
__device__ __forceinline__ void ldsm_x4(unsigned& r0, unsigned& r1,
                                        unsigned& r2, unsigned& r3, unsigned addr) {
    asm volatile("ldmatrix.sync.aligned.m8n8.x4.shared.b16 {%0,%1,%2,%3}, [%4];"
                 : "=r"(r0), "=r"(r1), "=r"(r2), "=r"(r3) : "r"(addr));
}
__device__ __forceinline__ void ldsm_x4_trans(unsigned& r0, unsigned& r1,
                                              unsigned& r2, unsigned& r3, unsigned addr) {
    asm volatile("ldmatrix.sync.aligned.m8n8.x4.trans.shared.b16 {%0,%1,%2,%3}, [%4];"
                 : "=r"(r0), "=r"(r1), "=r"(r2), "=r"(r3) : "r"(addr));
}
#define CP16(dst, src) \
    asm volatile("cp.async.cg.shared.global [%0], [%1], 16;" :: "r"(dst), "l"(src))

// ---------------------------------------------------------------------------
// fp32 -> bf16 weight convert, both weight matrices in one launch
// ---------------------------------------------------------------------------
__global__ void f2bf2(const float* __restrict__ s0, __nv_bfloat16* __restrict__ d0,
                      int n0, const float* __restrict__ s1,
                      __nv_bfloat16* __restrict__ d1, int n1)
{
    int i = (blockIdx.x * 256 + threadIdx.x) * 4;
    const float* s; __nv_bfloat16* d;
    if (i < n0) { s = s0; d = d0; }
    else        { s = s1 - n0; d = d1 - n0; if (i >= n0 + n1) return; }
    float4 v = *(const float4*)&s[i];
    *(unsigned*)&d[i]     = pack_bf16(v.x, v.y);
    *(unsigned*)&d[i + 2] = pack_bf16(v.z, v.w);
}

// ---------------------------------------------------------------------------
// GroupNorm pass 1: partial sums
// ---------------------------------------------------------------------------
__global__ void gn_partial(const float* __restrict__ x)
{
    int blk = blockIdx.x;
    int bg = blk >> 3, ck = blk & 7;
    const float* xb = x + (size_t)bg * 65536 + ck * 8192;
    float s = 0.f, ss = 0.f;
    for (int i = threadIdx.x; i < 2048; i += 256) {
        float4 v = *(const float4*)&xb[i * 4];
        s  += v.x + v.y + v.z + v.w;
        ss += v.x * v.x + v.y * v.y + v.z * v.z + v.w * v.w;
    }
    __shared__ float rs[256], rss[256];
    rs[threadIdx.x] = s; rss[threadIdx.x] = ss;
    __syncthreads();
    for (int off = 128; off > 0; off >>= 1) {
        if (threadIdx.x < off) {
            rs[threadIdx.x]  += rs[threadIdx.x + off];
            rss[threadIdx.x] += rss[threadIdx.x + off];
        }
        __syncthreads();
    }
    if (threadIdx.x == 0) {
        g_part[bg][ck][0] = rs[0];
        g_part[bg][ck][1] = rss[0];
    }
}

// ---------------------------------------------------------------------------
// GroupNorm pass 2: normalize + transpose -> normed_t[b][t][c] bf16.
// ---------------------------------------------------------------------------
__global__ void gn_apply_t(const float* __restrict__ x,
                           const float* __restrict__ w,
                           const float* __restrict__ bias,
                           __nv_bfloat16* __restrict__ out)
{
    int b  = blockIdx.y;
    int t0 = blockIdx.x * 64;
    int c0 = 2 * threadIdx.x;

    int g = c0 >> 4;
    float s = 0.f, ss = 0.f;
    #pragma unroll
    for (int i = 0; i < 8; i++) {
        s  += g_part[b * 16 + g][i][0];
        ss += g_part[b * 16 + g][i][1];
    }
    float mean = s * (1.f / 65536.f);
    float inv  = rsqrtf(ss * (1.f / 65536.f) - mean * mean + 1e-5f);
    float gm0 = w[c0] * inv,     bt0 = bias[c0] - mean * gm0;
    float gm1 = w[c0 + 1] * inv, bt1 = bias[c0 + 1] - mean * gm1;

    const float* x0 = x + ((size_t)b * 256 + c0) * T + t0;
    const float* x1 = x0 + T;
    __nv_bfloat16* ob = out + ((size_t)b * T + t0) * 256 + c0;

    #pragma unroll 4
    for (int i = 0; i < 16; i++) {
        float4 v0 = *(const float4*)&x0[i * 4];
        float4 v1 = *(const float4*)&x1[i * 4];
        *(unsigned*)&ob[(i * 4 + 0) * 256] = pack_bf16(v0.x * gm0 + bt0, v1.x * gm1 + bt1);
        *(unsigned*)&ob[(i * 4 + 1) * 256] = pack_bf16(v0.y * gm0 + bt0, v1.y * gm1 + bt1);
        *(unsigned*)&ob[(i * 4 + 2) * 256] = pack_bf16(v0.z * gm0 + bt0, v1.z * gm1 + bt1);
        *(unsigned*)&ob[(i * 4 + 3) * 256] = pack_bf16(v0.w * gm0 + bt0, v1.w * gm1 + bt1);
    }
}

// ---------------------------------------------------------------------------
// bf16 GEMM, ZERO-BARRIER: whole K=256 staged in smem, one cp.async wave,
// one sync, then 16 k-steps (128 MMAs/warp) with no synchronization.
// Tile 128(o) x 64(t). Rows 512B + 16B pad = 528B stride (bank-staggered).
// ---------------------------------------------------------------------------
#define GW_ROW 528
#define GX_OFF (128 * GW_ROW)              // 67584
#define GSM_TOTAL (GX_OFF + 64 * GW_ROW)   // 101376

__global__ void __launch_bounds__(256)
gemm_bf16(const __nv_bfloat16* __restrict__ W, const __nv_bfloat16* __restrict__ X,
          const float* __restrict__ bias, const float* __restrict__ res,
          void* __restrict__ out,
          size_t strideX, size_t strideO, size_t strideR, int bf16_out)
{
    extern __shared__ char gsm[];
    unsigned smbase = (unsigned)__cvta_generic_to_shared(gsm);

    int t0 = blockIdx.x * 64, o0 = blockIdx.y * 128, b = blockIdx.z;
    const __nv_bfloat16* Xb = X + (size_t)b * strideX;

    int tid = threadIdx.x, w = tid >> 5, lane = tid & 31;
    int qr = lane >> 2, ql = lane & 3;

    // ---- stage EVERYTHING: W 128x512B (2 thr/row), X 64x512B (4 thr/row) ----
    {
        int wrow = tid >> 1, wh = tid & 1;
        const char* wsrc = (const char*)(W + (size_t)(o0 + wrow) * 256) + wh * 256;
        unsigned wdst = smbase + wrow * GW_ROW + wh * 256;
        #pragma unroll
        for (int i = 0; i < 16; i++) CP16(wdst + i * 16, wsrc + i * 16);

        int xrow = tid >> 2, xh = tid & 3;
        const char* xsrc = (const char*)(Xb + (size_t)(t0 + xrow) * 256) + xh * 128;
        unsigned xdst = smbase + GX_OFF + xrow * GW_ROW + xh * 128;
        #pragma unroll
        for (int i = 0; i < 8; i++) CP16(xdst + i * 16, xsrc + i * 16);

        asm volatile("cp.async.commit_group;");
        asm volatile("cp.async.wait_group 0;" ::: "memory");
    }
    __syncthreads();   // the only barrier

    float acc[8][4] = {};
    unsigned abase = smbase + (16 * w + (lane & 15)) * GW_ROW + (lane >> 4) * 16;
    unsigned xbase = smbase + GX_OFF
                   + (((lane >> 4) << 3) + (lane & 7)) * GW_ROW
                   + ((lane >> 3) & 1) * 16;

    #pragma unroll
    for (int kk = 0; kk < 16; kk++) {
        unsigned a[4];
        ldsm_x4(a[0], a[1], a[2], a[3], abase + kk * 32);
        #pragma unroll
        for (int np = 0; np < 4; np++) {
            unsigned r0, r1, r2, r3;
            ldsm_x4(r0, r1, r2, r3, xbase + np * 16 * GW_ROW + kk * 32);
            mma_bf16(acc[2 * np],     a, r0, r1);
            mma_bf16(acc[2 * np + 1], a, r2, r3);
        }
    }

    int r0 = o0 + 16 * w + qr, r1 = r0 + 8;
    float bv0 = bias[r0], bv1 = bias[r1];
    if (bf16_out) {
        float s0 = ((r0 % 192) < 64) ? SCALE_Q : 1.0f;
        float s1 = ((r1 % 192) < 64) ? SCALE_Q : 1.0f;
        __nv_bfloat16* Ob = (__nv_bfloat16*)out + (size_t)b * strideO;
        #pragma unroll
        for (int nt = 0; nt < 8; nt++) {
            int t = t0 + nt * 8 + 2 * ql;
            *(unsigned*)&Ob[(size_t)r0 * T + t] =
                pack_bf16((acc[nt][0] + bv0) * s0, (acc[nt][1] + bv0) * s0);
            *(unsigned*)&Ob[(size_t)r1 * T + t] =
                pack_bf16((acc[nt][2] + bv1) * s1, (acc[nt][3] + bv1) * s1);
        }
    } else {
        float* Ob = (float*)out + (size_t)b * strideO;
        const float* Rb = res + (size_t)b * strideR;
        #pragma unroll
        for (int nt = 0; nt < 8; nt++) {
            int t = t0 + nt * 8 + 2 * ql;
            float2 v0 = make_float2(acc[nt][0] + bv0 + Rb[(size_t)r0 * T + t],
                                    acc[nt][1] + bv0 + Rb[(size_t)r0 * T + t + 1]);
            float2 v1 = make_float2(acc[nt][2] + bv1 + Rb[(size_t)r1 * T + t],
                                    acc[nt][3] + bv1 + Rb[(size_t)r1 * T + t + 1]);
            *(float2*)&Ob[(size_t)r0 * T + t] = v0;
            *(float2*)&Ob[(size_t)r1 * T + t] = v1;
        }
    }
}

// ---------------------------------------------------------------------------
// Flash attention (R11 measured best, reverted from R12): 4 warps x 32 query
// rows, 128 threads, 64-key tiles, 144B rows, bf16x2 ex2, ones-MMA row sums,
// 3-stage cp.async.
// ---------------------------------------------------------------------------
#define BM 128
#define PK 72                         // bf16 row stride: 144 B
#define KBYTES (64 * PK * 2)          // 9216 B per matrix per stage
#define STAGE_BYTES (2 * KBYTES)      // 18432 B
#define NSTAGE 3

__global__ void __launch_bounds__(128, 2)
attn_kernel(const __nv_bfloat16* __restrict__ qkv, __nv_bfloat16* __restrict__ hout)
{
    extern __shared__ char dsm[];
    unsigned smbase = (unsigned)__cvta_generic_to_shared(dsm);

    int t0 = blockIdx.x * BM;
    int bh = blockIdx.y;
    int b = bh >> 2, hd = bh & 3;
    const __nv_bfloat16* qp = qkv + ((size_t)b * 768 + (size_t)hd * 192) * T;
    const __nv_bfloat16* kp = qp + (size_t)64 * T;
    const __nv_bfloat16* vp = qp + (size_t)128 * T;

    int tid = threadIdx.x, w = tid >> 5, lane = tid & 31;
    int qr = lane >> 2, ql = lane & 3;

    int cam = tid >> 6;
    int car = tid & 63;
    const char* casrc = (const char*)((cam ? vp : kp) + (size_t)car * T);
    unsigned cadst0 = smbase + cam * KBYTES + car * 144;

    // ---- Q fragments: 2 m-tiles x 4 k-chunks x 4 regs ----
    unsigned qf[2][4][4];
    #pragma unroll
    for (int mt = 0; mt < 2; mt++) {
        int tq = t0 + 32 * w + 16 * mt + qr;
        #pragma unroll
        for (int kk = 0; kk < 4; kk++) {
            int c0 = kk * 16 + 2 * ql;
            #pragma unroll
            for (int h = 0; h < 2; h++) {
                unsigned short u0 = *(const unsigned short*)&qp[(size_t)c0 * T + tq + 8 * h];
                unsigned short u1 = *(const unsigned short*)&qp[(size_t)(c0 + 1) * T + tq + 8 * h];
                qf[mt][kk][h] = (unsigned)u0 | ((unsigned)u1 << 16);
                unsigned short u2 = *(const unsigned short*)&qp[(size_t)(c0 + 8) * T + tq + 8 * h];
                unsigned short u3 = *(const unsigned short*)&qp[(size_t)(c0 + 9) * T + tq + 8 * h];
                qf[mt][kk][h + 2] = (unsigned)u2 | ((unsigned)u3 << 16);
            }
        }
    }

    float o[2][8][4] = {};
    float lacc[2][4] = {};

    #pragma unroll
    for (int p = 0; p < 2; p++) {
        unsigned dst = cadst0 + p * STAGE_BYTES;
        const char* src = casrc + (size_t)p * 128;
        #pragma unroll
        for (int i = 0; i < 8; i++) CP16(dst + i * 16, src + i * 16);
        asm volatile("cp.async.commit_group;");
    }

    const int NT = T / 64;
    int st = 0;
    #pragma unroll 1
    for (int it = 0; it < NT; it++) {
        if (it + 1 < NT) {
            asm volatile("cp.async.wait_group 1;" ::: "memory");
        } else {
            asm volatile("cp.async.wait_group 0;" ::: "memory");
        }
        __syncthreads();

        if (it + 2 < NT) {
            int ps = (st + 2 >= NSTAGE) ? st + 2 - NSTAGE : st + 2;
            unsigned dst = cadst0 + ps * STAGE_BYTES;
            const char* src = casrc + (size_t)(it + 2) * 128;
            #pragma unroll
            for (int i = 0; i < 8; i++) CP16(dst + i * 16, src + i * 16);
            asm volatile("cp.async.commit_group;");
        }

        unsigned ksu = smbase + st * STAGE_BYTES;
        unsigned vsu = ksu + KBYTES;

        #pragma unroll
        for (int half = 0; half < 2; half++) {
            // ---- QK on 32 keys: S(log2 domain) ----
            float sf[2][4][4] = {};
            #pragma unroll
            for (int kk = 0; kk < 4; kk++) {
                unsigned base = ksu + (unsigned)((16 * kk + (lane & 15)) * 144)
                              + (unsigned)((lane >> 4) * 16) + half * 64u;
                #pragma unroll
                for (int npl = 0; npl < 2; npl++) {
                    unsigned r0, r1, r2, r3;
                    ldsm_x4_trans(r0, r1, r2, r3, base + npl * 32);
                    #pragma unroll
                    for (int mt = 0; mt < 2; mt++) {
                        mma_bf16(sf[mt][2 * npl],     qf[mt][kk], r0, r1);
                        mma_bf16(sf[mt][2 * npl + 1], qf[mt][kk], r2, r3);
                    }
                }
            }

            // ---- p = exp2(s): bf16x2 vector ex2, born-packed fragments ----
            unsigned pa[2][2][4];
            #pragma unroll
            for (int mt = 0; mt < 2; mt++) {
                #pragma unroll
                for (int nt = 0; nt < 4; nt++) {
                    int ks = nt >> 1, hi = (nt & 1) * 2;
                    pa[mt][ks][hi]     = ex2_bf16x2(pack_bf16(sf[mt][nt][0], sf[mt][nt][1]));
                    pa[mt][ks][hi + 1] = ex2_bf16x2(pack_bf16(sf[mt][nt][2], sf[mt][nt][3]));
                }
                mma_bf16(lacc[mt], pa[mt][0], ONES_BF16X2, ONES_BF16X2);
                mma_bf16(lacc[mt], pa[mt][1], ONES_BF16X2, ONES_BF16X2);
            }

            // ---- PV over this 32-key slice ----
            #pragma unroll
            for (int ks = 0; ks < 2; ks++) {
                int sc = 2 * half + ks;
                #pragma unroll
                for (int cp2 = 0; cp2 < 4; cp2++) {
                    int crow = cp2 * 16 + ((lane >> 4) << 3) + (lane & 7);
                    unsigned addr = vsu + (unsigned)(crow * 144)
                                  + (unsigned)(sc * 32 + ((lane >> 3) & 1) * 16);
                    unsigned r0, r1, r2, r3;
                    ldsm_x4(r0, r1, r2, r3, addr);
                    #pragma unroll
                    for (int mt = 0; mt < 2; mt++) {
                        mma_bf16(o[mt][2 * cp2],     pa[mt][ks], r0, r1);
                        mma_bf16(o[mt][2 * cp2 + 1], pa[mt][ks], r2, r3);
                    }
                }
            }
        }

        st = (st + 1 >= NSTAGE) ? 0 : st + 1;
    }

    // ---- epilogue: l already fully reduced by the ones-MMA ----
    __nv_bfloat16* hb = hout + (size_t)b * T * 256;
    #pragma unroll
    for (int mt = 0; mt < 2; mt++) {
        float i0 = 1.f / lacc[mt][0];
        float i1 = 1.f / lacc[mt][2];
        int tq = t0 + 32 * w + 16 * mt + qr;
        #pragma unroll
        for (int j = 0; j < 8; j++) {
            int c = hd * 64 + j * 8 + 2 * ql;
            *(unsigned*)&hb[(size_t)tq * 256 + c] =
                pack_bf16(o[mt][j][0] * i0, o[mt][j][1] * i0);
            *(unsigned*)&hb[(size_t)(tq + 8) * 256 + c] =
                pack_bf16(o[mt][j][2] * i1, o[mt][j][3] * i1);
        }
    }
}

// ---------------------------------------------------------------------------
// Launch
// ---------------------------------------------------------------------------
extern "C" void kernel_launch(void* const* d_in, const int* in_sizes, int n_in,
                              void* d_out, int out_size)
{
    const float* x      = (const float*)d_in[0];
    const float* norm_w = (const float*)d_in[1];
    const float* norm_b = (const float*)d_in[2];
    const float* qkv_w  = (const float*)d_in[3];
    const float* qkv_b  = (const float*)d_in[4];
    const float* proj_w = (const float*)d_in[5];
    const float* proj_b = (const float*)d_in[6];
    float* out = (float*)d_out;

    __nv_bfloat16 *normed_p, *qkv_p, *h_p, *wq_p, *wp_p;
    cudaGetSymbolAddress((void**)&normed_p, g_normed_t);
    cudaGetSymbolAddress((void**)&qkv_p,   g_qkv);
    cudaGetSymbolAddress((void**)&h_p,     g_ht);
    cudaGetSymbolAddress((void**)&wq_p,    g_wq);
    cudaGetSymbolAddress((void**)&wp_p,    g_wp);

    const int ATTN_SMEM = NSTAGE * STAGE_BYTES;   // 55296 B
    cudaFuncSetAttribute(attn_kernel, cudaFuncAttributeMaxDynamicSharedMemorySize,
                         ATTN_SMEM);
    cudaFuncSetAttribute(gemm_bf16, cudaFuncAttributeMaxDynamicSharedMemorySize,
                         GSM_TOTAL);              // 101376 B

    // 0. Weight conversion (fp32 -> bf16), single launch
    f2bf2<<<(768 * 256 + 256 * 256) / 1024, 256>>>(
        qkv_w, wq_p, 768 * 256, proj_w, wp_p, 256 * 256);

    // 1. GroupNorm (two-pass, transposed bf16 out)
    gn_partial<<<512, 256>>>(x);
    gn_apply_t<<<dim3(T / 64, B), 128>>>(x, norm_w, norm_b, normed_p);

    // 2. QKV GEMM (zero-barrier) -> [b][768][t] bf16, Q rows pre-scaled
    gemm_bf16<<<dim3(T / 64, 768 / 128, B), 256, GSM_TOTAL>>>(
        wq_p, normed_p, qkv_b, nullptr, qkv_p,
        (size_t)T * C, (size_t)768 * T, 0, 1);

    // 3. Flash attention -> h_t[b][t][c] bf16
    attn_kernel<<<dim3(T / BM, 16), 128, ATTN_SMEM>>>(qkv_p, h_p);

    // 4. Proj GEMM (zero-barrier) + bias + residual -> d_out fp32 [b][c][t]
    gemm_bf16<<<dim3(T / 64, 256 / 128, B), 256, GSM_TOTAL>>>(
        wp_p, h_p, proj_b, x, out,
        (size_t)T * C, (size_t)C * T, (size_t)C * T, 0);
}

// round 14
// speedup vs baseline: 1.0851x; 1.0851x over previous
#include <cuda_runtime.h>
#include <cuda_bf16.h>
#include <math.h>

#define T 4096
#define C 256
#define B 4

// Scratch (allocation-free rule: __device__ globals)
__device__ __nv_bfloat16 g_normed_t[B * T * C];      // [b][t][c] bf16
__device__ __nv_bfloat16 g_qkv[B * 3 * C * T];       // [b][768][t] bf16, q pre-scaled
__device__ __nv_bfloat16 g_ht[B * T * C];            // [b][t][c] bf16
__device__ __nv_bfloat16 g_wq[768 * 256];            // qkv_w bf16
__device__ __nv_bfloat16 g_wp[256 * 256];            // proj_w bf16
__device__ float g_part[64][8][2];

#define SCALE_Q 0.18033688f   // 0.125 * log2(e)
#define ONES_BF16X2 0x3F803F80u

// ---------------------------------------------------------------------------
// helpers
// ---------------------------------------------------------------------------
__device__ __forceinline__ unsigned pack_bf16(float a, float b) {
    __nv_bfloat162 h = __floats2bfloat162_rn(a, b);
    return *reinterpret_cast<unsigned*>(&h);
}
__device__ __forceinline__ unsigned ex2_bf16x2(unsigned x) {
    unsigned r;
    asm("ex2.approx.ftz.bf16x2 %0, %1;" : "=r"(r) : "r"(x));
    return r;
}
__device__ __forceinline__ void mma_bf16(float* d, const unsigned* a,
                                         unsigned b0, unsigned b1) {
    asm volatile(
        "mma.sync.aligned.m16n8k16.row.col.f32.bf16.bf16.f32 "
        "{%0,%1,%2,%3}, {%4,%5,%6,%7}, {%8,%9}, {%0,%1,%2,%3};"
        : "+f"(d[0]), "+f"(d[1]), "+f"(d[2]), "+f"(d[3])
        : "r"(a[0]), "r"(a[1]), "r"(a[2]), "r"(a[3]), "r"(b0), "r"(b1));
}
__device__ __forceinline__ void ldsm_x4(unsigned& r0, unsigned& r1,
                                        unsigned& r2, unsigned& r3, unsigned addr) {
    asm volatile("ldmatrix.sync.aligned.m8n8.x4.shared.b16 {%0,%1,%2,%3}, [%4];"
                 : "=r"(r0), "=r"(r1), "=r"(r2), "=r"(r3) : "r"(addr));
}
__device__ __forceinline__ void ldsm_x4_trans(unsigned& r0, unsigned& r1,
                                              unsigned& r2, unsigned& r3, unsigned addr) {
    asm volatile("ldmatrix.sync.aligned.m8n8.x4.trans.shared.b16 {%0,%1,%2,%3}, [%4];"
                 : "=r"(r0), "=r"(r1), "=r"(r2), "=r"(r3) : "r"(addr));
}
#define CP16(dst, src) \
    asm volatile("cp.async.cg.shared.global [%0], [%1], 16;" :: "r"(dst), "l"(src))

// ---------------------------------------------------------------------------
// Fused prep: blocks [0,512) compute GroupNorm partial sums;
// blocks [512,768) convert both weight matrices fp32 -> bf16.
// ---------------------------------------------------------------------------
__global__ void prep_kernel(const float* __restrict__ x,
                            const float* __restrict__ qkv_w,
                            __nv_bfloat16* __restrict__ wq,
                            const float* __restrict__ proj_w,
                            __nv_bfloat16* __restrict__ wp)
{
    if (blockIdx.x < 512) {
        int blk = blockIdx.x;
        int bg = blk >> 3, ck = blk & 7;
        const float* xb = x + (size_t)bg * 65536 + ck * 8192;
        float s = 0.f, ss = 0.f;
        for (int i = threadIdx.x; i < 2048; i += 256) {
            float4 v = *(const float4*)&xb[i * 4];
            s  += v.x + v.y + v.z + v.w;
            ss += v.x * v.x + v.y * v.y + v.z * v.z + v.w * v.w;
        }
        __shared__ float rs[256], rss[256];
        rs[threadIdx.x] = s; rss[threadIdx.x] = ss;
        __syncthreads();
        for (int off = 128; off > 0; off >>= 1) {
            if (threadIdx.x < off) {
                rs[threadIdx.x]  += rs[threadIdx.x + off];
                rss[threadIdx.x] += rss[threadIdx.x + off];
            }
            __syncthreads();
        }
        if (threadIdx.x == 0) {
            g_part[bg][ck][0] = rs[0];
            g_part[bg][ck][1] = rss[0];
        }
    } else {
        const int n0 = 768 * 256, n1 = 256 * 256;
        int i = ((blockIdx.x - 512) * 256 + threadIdx.x) * 4;
        const float* s; __nv_bfloat16* d;
        if (i < n0) { s = qkv_w; d = wq; }
        else        { s = proj_w - n0; d = wp - n0; if (i >= n0 + n1) return; }
        float4 v = *(const float4*)&s[i];
        *(unsigned*)&d[i]     = pack_bf16(v.x, v.y);
        *(unsigned*)&d[i + 2] = pack_bf16(v.z, v.w);
    }
}

// ---------------------------------------------------------------------------
// GroupNorm pass 2: normalize + transpose -> normed_t[b][t][c] bf16.
// ---------------------------------------------------------------------------
__global__ void gn_apply_t(const float* __restrict__ x,
                           const float* __restrict__ w,
                           const float* __restrict__ bias,
                           __nv_bfloat16* __restrict__ out)
{
    int b  = blockIdx.y;
    int t0 = blockIdx.x * 64;
    int c0 = 2 * threadIdx.x;

    int g = c0 >> 4;
    float s = 0.f, ss = 0.f;
    #pragma unroll
    for (int i = 0; i < 8; i++) {
        s  += g_part[b * 16 + g][i][0];
        ss += g_part[b * 16 + g][i][1];
    }
    float mean = s * (1.f / 65536.f);
    float inv  = rsqrtf(ss * (1.f / 65536.f) - mean * mean + 1e-5f);
    float gm0 = w[c0] * inv,     bt0 = bias[c0] - mean * gm0;
    float gm1 = w[c0 + 1] * inv, bt1 = bias[c0 + 1] - mean * gm1;

    const float* x0 = x + ((size_t)b * 256 + c0) * T + t0;
    const float* x1 = x0 + T;
    __nv_bfloat16* ob = out + ((size_t)b * T + t0) * 256 + c0;

    #pragma unroll 4
    for (int i = 0; i < 16; i++) {
        float4 v0 = *(const float4*)&x0[i * 4];
        float4 v1 = *(const float4*)&x1[i * 4];
        *(unsigned*)&ob[(i * 4 + 0) * 256] = pack_bf16(v0.x * gm0 + bt0, v1.x * gm1 + bt1);
        *(unsigned*)&ob[(i * 4 + 1) * 256] = pack_bf16(v0.y * gm0 + bt0, v1.y * gm1 + bt1);
        *(unsigned*)&ob[(i * 4 + 2) * 256] = pack_bf16(v0.z * gm0 + bt0, v1.z * gm1 + bt1);
        *(unsigned*)&ob[(i * 4 + 3) * 256] = pack_bf16(v0.w * gm0 + bt0, v1.w * gm1 + bt1);
    }
}

// ---------------------------------------------------------------------------
// bf16 GEMM, k-step 32, ldmatrix + 3-stage cp.async (R10/R11 measured best).
// Tile 128(o) x 64(t). Rows 64B + 16B pad = 80B stride.
// ---------------------------------------------------------------------------
#define GW_ROW 80
#define GW_BYTES (128 * GW_ROW)            // 10240
#define GX_BYTES (64 * GW_ROW)             // 5120
#define GSTAGE (GW_BYTES + GX_BYTES)       // 15360
#define GNST 3

__global__ void __launch_bounds__(256)
gemm_bf16(const __nv_bfloat16* __restrict__ W, const __nv_bfloat16* __restrict__ X,
          const float* __restrict__ bias, const float* __restrict__ res,
          void* __restrict__ out,
          size_t strideX, size_t strideO, size_t strideR, int bf16_out)
{
    __shared__ char gsm[GNST * GSTAGE];
    unsigned smbase = (unsigned)__cvta_generic_to_shared(gsm);

    int t0 = blockIdx.x * 64, o0 = blockIdx.y * 128, b = blockIdx.z;
    const __nv_bfloat16* Xb = X + (size_t)b * strideX;

    int tid = threadIdx.x, w = tid >> 5, lane = tid & 31;
    int qr = lane >> 2, ql = lane & 3;

    int wrow = tid >> 1, wh = (tid & 1);
    const __nv_bfloat16* wsrc = W + (size_t)(o0 + wrow) * 256 + wh * 16;
    unsigned wdst = wrow * GW_ROW + wh * 32;
    int xrow = (tid & 127) >> 1, xh = (tid & 1);
    const __nv_bfloat16* xsrc = Xb + (size_t)(t0 + xrow) * 256 + xh * 16;
    unsigned xdst = GW_BYTES + xrow * GW_ROW + xh * 32;

    float acc[8][4] = {};

    #pragma unroll
    for (int p = 0; p < 2; p++) {
        unsigned st = smbase + p * GSTAGE;
        CP16(st + wdst, wsrc + p * 32); CP16(st + wdst + 16, wsrc + p * 32 + 8);
        if (tid < 128) {
            CP16(st + xdst, xsrc + p * 32); CP16(st + xdst + 16, xsrc + p * 32 + 8);
        }
        asm volatile("cp.async.commit_group;");
    }

    int st = 0;
    #pragma unroll 1
    for (int it = 0; it < 8; it++) {
        if (it + 1 < 8) {
            asm volatile("cp.async.wait_group 1;" ::: "memory");
        } else {
            asm volatile("cp.async.wait_group 0;" ::: "memory");
        }
        __syncthreads();

        if (it + 2 < 8) {
            int ps = (st + 2 >= GNST) ? st + 2 - GNST : st + 2;
            unsigned sb = smbase + ps * GSTAGE;
            CP16(sb + wdst, wsrc + (it + 2) * 32);
            CP16(sb + wdst + 16, wsrc + (it + 2) * 32 + 8);
            if (tid < 128) {
                CP16(sb + xdst, xsrc + (it + 2) * 32);
                CP16(sb + xdst + 16, xsrc + (it + 2) * 32 + 8);
            }
            asm volatile("cp.async.commit_group;");
        }

        unsigned wst = smbase + st * GSTAGE;
        unsigned xst = wst + GW_BYTES;

        unsigned a[2][4];
        unsigned abase = wst + (16 * w + (lane & 15)) * GW_ROW + (lane >> 4) * 16;
        ldsm_x4(a[0][0], a[0][1], a[0][2], a[0][3], abase);
        ldsm_x4(a[1][0], a[1][1], a[1][2], a[1][3], abase + 32);
        #pragma unroll
        for (int kh = 0; kh < 2; kh++) {
            #pragma unroll
            for (int np = 0; np < 4; np++) {
                int crow = np * 16 + ((lane >> 4) << 3) + (lane & 7);
                unsigned r0, r1, r2, r3;
                ldsm_x4(r0, r1, r2, r3,
                        xst + crow * GW_ROW + kh * 32 + ((lane >> 3) & 1) * 16);
                mma_bf16(acc[2 * np],     a[kh], r0, r1);
                mma_bf16(acc[2 * np + 1], a[kh], r2, r3);
            }
        }

        st = (st + 1 >= GNST) ? 0 : st + 1;
    }

    int r0 = o0 + 16 * w + qr, r1 = r0 + 8;
    float bv0 = bias[r0], bv1 = bias[r1];
    if (bf16_out) {
        float s0 = ((r0 % 192) < 64) ? SCALE_Q : 1.0f;
        float s1 = ((r1 % 192) < 64) ? SCALE_Q : 1.0f;
        __nv_bfloat16* Ob = (__nv_bfloat16*)out + (size_t)b * strideO;
        #pragma unroll
        for (int nt = 0; nt < 8; nt++) {
            int t = t0 + nt * 8 + 2 * ql;
            *(unsigned*)&Ob[(size_t)r0 * T + t] =
                pack_bf16((acc[nt][0] + bv0) * s0, (acc[nt][1] + bv0) * s0);
            *(unsigned*)&Ob[(size_t)r1 * T + t] =
                pack_bf16((acc[nt][2] + bv1) * s1, (acc[nt][3] + bv1) * s1);
        }
    } else {
        float* Ob = (float*)out + (size_t)b * strideO;
        const float* Rb = res + (size_t)b * strideR;
        #pragma unroll
        for (int nt = 0; nt < 8; nt++) {
            int t = t0 + nt * 8 + 2 * ql;
            float2 v0 = make_float2(acc[nt][0] + bv0 + Rb[(size_t)r0 * T + t],
                                    acc[nt][1] + bv0 + Rb[(size_t)r0 * T + t + 1]);
            float2 v1 = make_float2(acc[nt][2] + bv1 + Rb[(size_t)r1 * T + t],
                                    acc[nt][3] + bv1 + Rb[(size_t)r1 * T + t + 1]);
            *(float2*)&Ob[(size_t)r0 * T + t] = v0;
            *(float2*)&Ob[(size_t)r1 * T + t] = v1;
        }
    }
}

// ---------------------------------------------------------------------------
// Flash attention (R11 measured best): 4 warps x 32 query rows, 128 threads,
// 64-key tiles, 144B rows, bf16x2 ex2, ones-MMA row sums, 3-stage cp.async.
// ---------------------------------------------------------------------------
#define BM 128
#define PK 72                         // bf16 row stride: 144 B
#define KBYTES (64 * PK * 2)          // 9216 B per matrix per stage
#define STAGE_BYTES (2 * KBYTES)      // 18432 B
#define NSTAGE 3

__global__ void __launch_bounds__(128, 2)
attn_kernel(const __nv_bfloat16* __restrict__ qkv, __nv_bfloat16* __restrict__ hout)
{
    extern __shared__ char dsm[];
    unsigned smbase = (unsigned)__cvta_generic_to_shared(dsm);

    int t0 = blockIdx.x * BM;
    int bh = blockIdx.y;
    int b = bh >> 2, hd = bh & 3;
    const __nv_bfloat16* qp = qkv + ((size_t)b * 768 + (size_t)hd * 192) * T;
    const __nv_bfloat16* kp = qp + (size_t)64 * T;
    const __nv_bfloat16* vp = qp + (size_t)128 * T;

    int tid = threadIdx.x, w = tid >> 5, lane = tid & 31;
    int qr = lane >> 2, ql = lane & 3;

    int cam = tid >> 6;
    int car = tid & 63;
    const char* casrc = (const char*)((cam ? vp : kp) + (size_t)car * T);
    unsigned cadst0 = smbase + cam * KBYTES + car * 144;

    // ---- Q fragments: 2 m-tiles x 4 k-chunks x 4 regs ----
    unsigned qf[2][4][4];
    #pragma unroll
    for (int mt = 0; mt < 2; mt++) {
        int tq = t0 + 32 * w + 16 * mt + qr;
        #pragma unroll
        for (int kk = 0; kk < 4; kk++) {
            int c0 = kk * 16 + 2 * ql;
            #pragma unroll
            for (int h = 0; h < 2; h++) {
                unsigned short u0 = *(const unsigned short*)&qp[(size_t)c0 * T + tq + 8 * h];
                unsigned short u1 = *(const unsigned short*)&qp[(size_t)(c0 + 1) * T + tq + 8 * h];
                qf[mt][kk][h] = (unsigned)u0 | ((unsigned)u1 << 16);
                unsigned short u2 = *(const unsigned short*)&qp[(size_t)(c0 + 8) * T + tq + 8 * h];
                unsigned short u3 = *(const unsigned short*)&qp[(size_t)(c0 + 9) * T + tq + 8 * h];
                qf[mt][kk][h + 2] = (unsigned)u2 | ((unsigned)u3 << 16);
            }
        }
    }

    float o[2][8][4] = {};
    float lacc[2][4] = {};

    #pragma unroll
    for (int p = 0; p < 2; p++) {
        unsigned dst = cadst0 + p * STAGE_BYTES;
        const char* src = casrc + (size_t)p * 128;
        #pragma unroll
        for (int i = 0; i < 8; i++) CP16(dst + i * 16, src + i * 16);
        asm volatile("cp.async.commit_group;");
    }

    const int NT = T / 64;
    int st = 0;
    #pragma unroll 1
    for (int it = 0; it < NT; it++) {
        if (it + 1 < NT) {
            asm volatile("cp.async.wait_group 1;" ::: "memory");
        } else {
            asm volatile("cp.async.wait_group 0;" ::: "memory");
        }
        __syncthreads();

        if (it + 2 < NT) {
            int ps = (st + 2 >= NSTAGE) ? st + 2 - NSTAGE : st + 2;
            unsigned dst = cadst0 + ps * STAGE_BYTES;
            const char* src = casrc + (size_t)(it + 2) * 128;
            #pragma unroll
            for (int i = 0; i < 8; i++) CP16(dst + i * 16, src + i * 16);
            asm volatile("cp.async.commit_group;");
        }

        unsigned ksu = smbase + st * STAGE_BYTES;
        unsigned vsu = ksu + KBYTES;

        #pragma unroll
        for (int half = 0; half < 2; half++) {
            // ---- QK on 32 keys: S(log2 domain) ----
            float sf[2][4][4] = {};
            #pragma unroll
            for (int kk = 0; kk < 4; kk++) {
                unsigned base = ksu + (unsigned)((16 * kk + (lane & 15)) * 144)
                              + (unsigned)((lane >> 4) * 16) + half * 64u;
                #pragma unroll
                for (int npl = 0; npl < 2; npl++) {
                    unsigned r0, r1, r2, r3;
                    ldsm_x4_trans(r0, r1, r2, r3, base + npl * 32);
                    #pragma unroll
                    for (int mt = 0; mt < 2; mt++) {
                        mma_bf16(sf[mt][2 * npl],     qf[mt][kk], r0, r1);
                        mma_bf16(sf[mt][2 * npl + 1], qf[mt][kk], r2, r3);
                    }
                }
            }

            // ---- p = exp2(s): bf16x2 vector ex2, born-packed fragments ----
            unsigned pa[2][2][4];
            #pragma unroll
            for (int mt = 0; mt < 2; mt++) {
                #pragma unroll
                for (int nt = 0; nt < 4; nt++) {
                    int ks = nt >> 1, hi = (nt & 1) * 2;
                    pa[mt][ks][hi]     = ex2_bf16x2(pack_bf16(sf[mt][nt][0], sf[mt][nt][1]));
                    pa[mt][ks][hi + 1] = ex2_bf16x2(pack_bf16(sf[mt][nt][2], sf[mt][nt][3]));
                }
                mma_bf16(lacc[mt], pa[mt][0], ONES_BF16X2, ONES_BF16X2);
                mma_bf16(lacc[mt], pa[mt][1], ONES_BF16X2, ONES_BF16X2);
            }

            // ---- PV over this 32-key slice ----
            #pragma unroll
            for (int ks = 0; ks < 2; ks++) {
                int sc = 2 * half + ks;
                #pragma unroll
                for (int cp2 = 0; cp2 < 4; cp2++) {
                    int crow = cp2 * 16 + ((lane >> 4) << 3) + (lane & 7);
                    unsigned addr = vsu + (unsigned)(crow * 144)
                                  + (unsigned)(sc * 32 + ((lane >> 3) & 1) * 16);
                    unsigned r0, r1, r2, r3;
                    ldsm_x4(r0, r1, r2, r3, addr);
                    #pragma unroll
                    for (int mt = 0; mt < 2; mt++) {
                        mma_bf16(o[mt][2 * cp2],     pa[mt][ks], r0, r1);
                        mma_bf16(o[mt][2 * cp2 + 1], pa[mt][ks], r2, r3);
                    }
                }
            }
        }

        st = (st + 1 >= NSTAGE) ? 0 : st + 1;
    }

    // ---- epilogue: l already fully reduced by the ones-MMA ----
    __nv_bfloat16* hb = hout + (size_t)b * T * 256;
    #pragma unroll
    for (int mt = 0; mt < 2; mt++) {
        float i0 = 1.f / lacc[mt][0];
        float i1 = 1.f / lacc[mt][2];
        int tq = t0 + 32 * w + 16 * mt + qr;
        #pragma unroll
        for (int j = 0; j < 8; j++) {
            int c = hd * 64 + j * 8 + 2 * ql;
            *(unsigned*)&hb[(size_t)tq * 256 + c] =
                pack_bf16(o[mt][j][0] * i0, o[mt][j][1] * i0);
            *(unsigned*)&hb[(size_t)(tq + 8) * 256 + c] =
                pack_bf16(o[mt][j][2] * i1, o[mt][j][3] * i1);
        }
    }
}

// ---------------------------------------------------------------------------
// Launch
// ---------------------------------------------------------------------------
extern "C" void kernel_launch(void* const* d_in, const int* in_sizes, int n_in,
                              void* d_out, int out_size)
{
    const float* x      = (const float*)d_in[0];
    const float* norm_w = (const float*)d_in[1];
    const float* norm_b = (const float*)d_in[2];
    const float* qkv_w  = (const float*)d_in[3];
    const float* qkv_b  = (const float*)d_in[4];
    const float* proj_w = (const float*)d_in[5];
    const float* proj_b = (const float*)d_in[6];
    float* out = (float*)d_out;

    __nv_bfloat16 *normed_p, *qkv_p, *h_p, *wq_p, *wp_p;
    cudaGetSymbolAddress((void**)&normed_p, g_normed_t);
    cudaGetSymbolAddress((void**)&qkv_p,   g_qkv);
    cudaGetSymbolAddress((void**)&h_p,     g_ht);
    cudaGetSymbolAddress((void**)&wq_p,    g_wq);
    cudaGetSymbolAddress((void**)&wp_p,    g_wp);

    const int ATTN_SMEM = NSTAGE * STAGE_BYTES;   // 55296 B
    cudaFuncSetAttribute(attn_kernel, cudaFuncAttributeMaxDynamicSharedMemorySize,
                         ATTN_SMEM);

    // 0+1a. Fused prep: GN partial sums + weight conversion (one launch)
    prep_kernel<<<768, 256>>>(x, qkv_w, wq_p, proj_w, wp_p);

    // 1b. GroupNorm apply + transpose -> bf16 [b][t][c]
    gn_apply_t<<<dim3(T / 64, B), 128>>>(x, norm_w, norm_b, normed_p);

    // 2. QKV GEMM -> [b][768][t] bf16, Q rows pre-scaled
    gemm_bf16<<<dim3(T / 64, 768 / 128, B), 256>>>(
        wq_p, normed_p, qkv_b, nullptr, qkv_p,
        (size_t)T * C, (size_t)768 * T, 0, 1);

    // 3. Flash attention -> h_t[b][t][c] bf16
    attn_kernel<<<dim3(T / BM, 16), 128, ATTN_SMEM>>>(qkv_p, h_p);

    // 4. Proj GEMM + bias + residual -> d_out fp32 [b][c][t]
    gemm_bf16<<<dim3(T / 64, 256 / 128, B), 256>>>(
        wp_p, h_p, proj_b, x, out,
        (size_t)T * C, (size_t)C * T, (size_t)C * T, 0);
}

// round 16
// speedup vs baseline: 1.0997x; 1.0134x over previous
#include <cuda_runtime.h>
#include <cuda_bf16.h>
#include <math.h>

#define T 4096
#define C 256
#define B 4

// Scratch (allocation-free rule: __device__ globals)
__device__ __nv_bfloat16 g_normed_t[B * T * C];      // [b][t][c] bf16
__device__ __nv_bfloat16 g_qkv[B * 3 * C * T];       // [b][768][t] bf16, q pre-scaled
__device__ __nv_bfloat16 g_ht[B * T * C];            // [b][t][c] bf16
__device__ __nv_bfloat16 g_wq[768 * 256];            // qkv_w bf16
__device__ __nv_bfloat16 g_wp[256 * 256];            // proj_w bf16
__device__ float g_part[64][8][2];

#define SCALE_Q 0.18033688f   // 0.125 * log2(e)
#define ONES_BF16X2 0x3F803F80u

// ---------------------------------------------------------------------------
// helpers
// ---------------------------------------------------------------------------
__device__ __forceinline__ unsigned pack_bf16(float a, float b) {
    __nv_bfloat162 h = __floats2bfloat162_rn(a, b);
    return *reinterpret_cast<unsigned*>(&h);
}
__device__ __forceinline__ unsigned ex2_bf16x2(unsigned x) {
    unsigned r;
    asm("ex2.approx.ftz.bf16x2 %0, %1;" : "=r"(r) : "r"(x));
    return r;
}
__device__ __forceinline__ void mma_bf16(float* d, const unsigned* a,
                                         unsigned b0, unsigned b1) {
    asm volatile(
        "mma.sync.aligned.m16n8k16.row.col.f32.bf16.bf16.f32 "
        "{%0,%1,%2,%3}, {%4,%5,%6,%7}, {%8,%9}, {%0,%1,%2,%3};"
        : "+f"(d[0]), "+f"(d[1]), "+f"(d[2]), "+f"(d[3])
        : "r"(a[0]), "r"(a[1]), "r"(a[2]), "r"(a[3]), "r"(b0), "r"(b1));
}
__device__ __forceinline__ void ldsm_x4(unsigned& r0, unsigned& r1,
                                        unsigned& r2, unsigned& r3, unsigned addr) {
    asm volatile("ldmatrix.sync.aligned.m8n8.x4.shared.b16 {%0,%1,%2,%3}, [%4];"
                 : "=r"(r0), "=r"(r1), "=r"(r2), "=r"(r3) : "r"(addr));
}
__device__ __forceinline__ void ldsm_x4_trans(unsigned& r0, unsigned& r1,
                                              unsigned& r2, unsigned& r3, unsigned addr) {
    asm volatile("ldmatrix.sync.aligned.m8n8.x4.trans.shared.b16 {%0,%1,%2,%3}, [%4];"
                 : "=r"(r0), "=r"(r1), "=r"(r2), "=r"(r3) : "r"(addr));
}
#define CP16(dst, src) \
    asm volatile("cp.async.cg.shared.global [%0], [%1], 16;" :: "r"(dst), "l"(src))

// ---------------------------------------------------------------------------
// Fused prep: blocks [0,512) GroupNorm partial sums; [512,768) weight convert.
// ---------------------------------------------------------------------------
__global__ void prep_kernel(const float* __restrict__ x,
                            const float* __restrict__ qkv_w,
                            __nv_bfloat16* __restrict__ wq,
                            const float* __restrict__ proj_w,
                            __nv_bfloat16* __restrict__ wp)
{
    if (blockIdx.x < 512) {
        int blk = blockIdx.x;
        int bg = blk >> 3, ck = blk & 7;
        const float* xb = x + (size_t)bg * 65536 + ck * 8192;
        float s = 0.f, ss = 0.f;
        for (int i = threadIdx.x; i < 2048; i += 256) {
            float4 v = *(const float4*)&xb[i * 4];
            s  += v.x + v.y + v.z + v.w;
            ss += v.x * v.x + v.y * v.y + v.z * v.z + v.w * v.w;
        }
        __shared__ float rs[256], rss[256];
        rs[threadIdx.x] = s; rss[threadIdx.x] = ss;
        __syncthreads();
        for (int off = 128; off > 0; off >>= 1) {
            if (threadIdx.x < off) {
                rs[threadIdx.x]  += rs[threadIdx.x + off];
                rss[threadIdx.x] += rss[threadIdx.x + off];
            }
            __syncthreads();
        }
        if (threadIdx.x == 0) {
            g_part[bg][ck][0] = rs[0];
            g_part[bg][ck][1] = rss[0];
        }
    } else {
        const int n0 = 768 * 256, n1 = 256 * 256;
        int i = ((blockIdx.x - 512) * 256 + threadIdx.x) * 4;
        const float* s; __nv_bfloat16* d;
        if (i < n0) { s = qkv_w; d = wq; }
        else        { s = proj_w - n0; d = wp - n0; if (i >= n0 + n1) return; }
        float4 v = *(const float4*)&s[i];
        *(unsigned*)&d[i]     = pack_bf16(v.x, v.y);
        *(unsigned*)&d[i + 2] = pack_bf16(v.z, v.w);
    }
}

// ---------------------------------------------------------------------------
// GroupNorm pass 2: normalize + transpose -> normed_t[b][t][c] bf16.
// ---------------------------------------------------------------------------
__global__ void gn_apply_t(const float* __restrict__ x,
                           const float* __restrict__ w,
                           const float* __restrict__ bias,
                           __nv_bfloat16* __restrict__ out)
{
    int b  = blockIdx.y;
    int t0 = blockIdx.x * 64;
    int c0 = 2 * threadIdx.x;

    int g = c0 >> 4;
    float s = 0.f, ss = 0.f;
    #pragma unroll
    for (int i = 0; i < 8; i++) {
        s  += g_part[b * 16 + g][i][0];
        ss += g_part[b * 16 + g][i][1];
    }
    float mean = s * (1.f / 65536.f);
    float inv  = rsqrtf(ss * (1.f / 65536.f) - mean * mean + 1e-5f);
    float gm0 = w[c0] * inv,     bt0 = bias[c0] - mean * gm0;
    float gm1 = w[c0 + 1] * inv, bt1 = bias[c0 + 1] - mean * gm1;

    const float* x0 = x + ((size_t)b * 256 + c0) * T + t0;
    const float* x1 = x0 + T;
    __nv_bfloat16* ob = out + ((size_t)b * T + t0) * 256 + c0;

    #pragma unroll 4
    for (int i = 0; i < 16; i++) {
        float4 v0 = *(const float4*)&x0[i * 4];
        float4 v1 = *(const float4*)&x1[i * 4];
        *(unsigned*)&ob[(i * 4 + 0) * 256] = pack_bf16(v0.x * gm0 + bt0, v1.x * gm1 + bt1);
        *(unsigned*)&ob[(i * 4 + 1) * 256] = pack_bf16(v0.y * gm0 + bt0, v1.y * gm1 + bt1);
        *(unsigned*)&ob[(i * 4 + 2) * 256] = pack_bf16(v0.z * gm0 + bt0, v1.z * gm1 + bt1);
        *(unsigned*)&ob[(i * 4 + 3) * 256] = pack_bf16(v0.w * gm0 + bt0, v1.w * gm1 + bt1);
    }
}

// ---------------------------------------------------------------------------
// bf16 GEMM, tile 128(o) x 128(t), k-step 32, 3-stage cp.async.
// Halves W re-reads from L2 vs the 64-wide t-tile.
// ---------------------------------------------------------------------------
#define GW_ROW 80
#define GW_BYTES (128 * GW_ROW)            // 10240
#define GX_BYTES (128 * GW_ROW)            // 10240
#define GSTAGE (GW_BYTES + GX_BYTES)       // 20480
#define GNST 3
#define GSM_TOTAL (GNST * GSTAGE)          // 61440

__global__ void __launch_bounds__(256)
gemm_bf16(const __nv_bfloat16* __restrict__ W, const __nv_bfloat16* __restrict__ X,
          const float* __restrict__ bias, const float* __restrict__ res,
          void* __restrict__ out,
          size_t strideX, size_t strideO, size_t strideR, int bf16_out)
{
    extern __shared__ char gsm[];
    unsigned smbase = (unsigned)__cvta_generic_to_shared(gsm);

    int t0 = blockIdx.x * 128, o0 = blockIdx.y * 128, b = blockIdx.z;
    const __nv_bfloat16* Xb = X + (size_t)b * strideX;

    int tid = threadIdx.x, w = tid >> 5, lane = tid & 31;
    int qr = lane >> 2, ql = lane & 3;

    // cp.async roles: W and X both 128 rows x 2 32B halves (256 threads each)
    int row = tid >> 1, h = tid & 1;
    const __nv_bfloat16* wsrc = W + (size_t)(o0 + row) * 256 + h * 16;
    unsigned wdst = row * GW_ROW + h * 32;
    const __nv_bfloat16* xsrc = Xb + (size_t)(t0 + row) * 256 + h * 16;
    unsigned xdst = GW_BYTES + row * GW_ROW + h * 32;

    float acc[16][4] = {};

    #pragma unroll
    for (int p = 0; p < 2; p++) {
        unsigned st = smbase + p * GSTAGE;
        CP16(st + wdst, wsrc + p * 32); CP16(st + wdst + 16, wsrc + p * 32 + 8);
        CP16(st + xdst, xsrc + p * 32); CP16(st + xdst + 16, xsrc + p * 32 + 8);
        asm volatile("cp.async.commit_group;");
    }

    int st = 0;
    #pragma unroll 1
    for (int it = 0; it < 8; it++) {
        if (it + 1 < 8) {
            asm volatile("cp.async.wait_group 1;" ::: "memory");
        } else {
            asm volatile("cp.async.wait_group 0;" ::: "memory");
        }
        __syncthreads();

        if (it + 2 < 8) {
            int ps = (st + 2 >= GNST) ? st + 2 - GNST : st + 2;
            unsigned sb = smbase + ps * GSTAGE;
            CP16(sb + wdst, wsrc + (it + 2) * 32);
            CP16(sb + wdst + 16, wsrc + (it + 2) * 32 + 8);
            CP16(sb + xdst, xsrc + (it + 2) * 32);
            CP16(sb + xdst + 16, xsrc + (it + 2) * 32 + 8);
            asm volatile("cp.async.commit_group;");
        }

        unsigned wst = smbase + st * GSTAGE;
        unsigned xst = wst + GW_BYTES;

        unsigned a[2][4];
        unsigned abase = wst + (16 * w + (lane & 15)) * GW_ROW + (lane >> 4) * 16;
        ldsm_x4(a[0][0], a[0][1], a[0][2], a[0][3], abase);
        ldsm_x4(a[1][0], a[1][1], a[1][2], a[1][3], abase + 32);
        #pragma unroll
        for (int kh = 0; kh < 2; kh++) {
            #pragma unroll
            for (int np = 0; np < 8; np++) {
                int crow = np * 16 + ((lane >> 4) << 3) + (lane & 7);
                unsigned r0, r1, r2, r3;
                ldsm_x4(r0, r1, r2, r3,
                        xst + crow * GW_ROW + kh * 32 + ((lane >> 3) & 1) * 16);
                mma_bf16(acc[2 * np],     a[kh], r0, r1);
                mma_bf16(acc[2 * np + 1], a[kh], r2, r3);
            }
        }

        st = (st + 1 >= GNST) ? 0 : st + 1;
    }

    int r0 = o0 + 16 * w + qr, r1 = r0 + 8;
    float bv0 = bias[r0], bv1 = bias[r1];
    if (bf16_out) {
        float s0 = ((r0 % 192) < 64) ? SCALE_Q : 1.0f;
        float s1 = ((r1 % 192) < 64) ? SCALE_Q : 1.0f;
        __nv_bfloat16* Ob = (__nv_bfloat16*)out + (size_t)b * strideO;
        #pragma unroll
        for (int nt = 0; nt < 16; nt++) {
            int t = t0 + nt * 8 + 2 * ql;
            *(unsigned*)&Ob[(size_t)r0 * T + t] =
                pack_bf16((acc[nt][0] + bv0) * s0, (acc[nt][1] + bv0) * s0);
            *(unsigned*)&Ob[(size_t)r1 * T + t] =
                pack_bf16((acc[nt][2] + bv1) * s1, (acc[nt][3] + bv1) * s1);
        }
    } else {
        float* Ob = (float*)out + (size_t)b * strideO;
        const float* Rb = res + (size_t)b * strideR;
        #pragma unroll
        for (int nt = 0; nt < 16; nt++) {
            int t = t0 + nt * 8 + 2 * ql;
            float2 v0 = make_float2(acc[nt][0] + bv0 + Rb[(size_t)r0 * T + t],
                                    acc[nt][1] + bv0 + Rb[(size_t)r0 * T + t + 1]);
            float2 v1 = make_float2(acc[nt][2] + bv1 + Rb[(size_t)r1 * T + t],
                                    acc[nt][3] + bv1 + Rb[(size_t)r1 * T + t + 1]);
            *(float2*)&Ob[(size_t)r0 * T + t] = v0;
            *(float2*)&Ob[(size_t)r1 * T + t] = v1;
        }
    }
}

// ---------------------------------------------------------------------------
// Flash attention (R11/R14 measured best): 4 warps x 32 query rows, 128 thr,
// 64-key tiles, 144B rows, bf16x2 ex2, ones-MMA row sums, 3-stage cp.async.
// ---------------------------------------------------------------------------
#define BM 128
#define PK 72                         // bf16 row stride: 144 B
#define KBYTES (64 * PK * 2)          // 9216 B per matrix per stage
#define STAGE_BYTES (2 * KBYTES)      // 18432 B
#define NSTAGE 3

__global__ void __launch_bounds__(128, 2)
attn_kernel(const __nv_bfloat16* __restrict__ qkv, __nv_bfloat16* __restrict__ hout)
{
    extern __shared__ char dsm[];
    unsigned smbase = (unsigned)__cvta_generic_to_shared(dsm);

    int t0 = blockIdx.x * BM;
    int bh = blockIdx.y;
    int b = bh >> 2, hd = bh & 3;
    const __nv_bfloat16* qp = qkv + ((size_t)b * 768 + (size_t)hd * 192) * T;
    const __nv_bfloat16* kp = qp + (size_t)64 * T;
    const __nv_bfloat16* vp = qp + (size_t)128 * T;

    int tid = threadIdx.x, w = tid >> 5, lane = tid & 31;
    int qr = lane >> 2, ql = lane & 3;

    int cam = tid >> 6;
    int car = tid & 63;
    const char* casrc = (const char*)((cam ? vp : kp) + (size_t)car * T);
    unsigned cadst0 = smbase + cam * KBYTES + car * 144;

    // ---- Q fragments: 2 m-tiles x 4 k-chunks x 4 regs ----
    unsigned qf[2][4][4];
    #pragma unroll
    for (int mt = 0; mt < 2; mt++) {
        int tq = t0 + 32 * w + 16 * mt + qr;
        #pragma unroll
        for (int kk = 0; kk < 4; kk++) {
            int c0 = kk * 16 + 2 * ql;
            #pragma unroll
            for (int h = 0; h < 2; h++) {
                unsigned short u0 = *(const unsigned short*)&qp[(size_t)c0 * T + tq + 8 * h];
                unsigned short u1 = *(const unsigned short*)&qp[(size_t)(c0 + 1) * T + tq + 8 * h];
                qf[mt][kk][h] = (unsigned)u0 | ((unsigned)u1 << 16);
                unsigned short u2 = *(const unsigned short*)&qp[(size_t)(c0 + 8) * T + tq + 8 * h];
                unsigned short u3 = *(const unsigned short*)&qp[(size_t)(c0 + 9) * T + tq + 8 * h];
                qf[mt][kk][h + 2] = (unsigned)u2 | ((unsigned)u3 << 16);
            }
        }
    }

    float o[2][8][4] = {};
    float lacc[2][4] = {};

    #pragma unroll
    for (int p = 0; p < 2; p++) {
        unsigned dst = cadst0 + p * STAGE_BYTES;
        const char* src = casrc + (size_t)p * 128;
        #pragma unroll
        for (int i = 0; i < 8; i++) CP16(dst + i * 16, src + i * 16);
        asm volatile("cp.async.commit_group;");
    }

    const int NT = T / 64;
    int st = 0;
    #pragma unroll 1
    for (int it = 0; it < NT; it++) {
        if (it + 1 < NT) {
            asm volatile("cp.async.wait_group 1;" ::: "memory");
        } else {
            asm volatile("cp.async.wait_group 0;" ::: "memory");
        }
        __syncthreads();

        if (it + 2 < NT) {
            int ps = (st + 2 >= NSTAGE) ? st + 2 - NSTAGE : st + 2;
            unsigned dst = cadst0 + ps * STAGE_BYTES;
            const char* src = casrc + (size_t)(it + 2) * 128;
            #pragma unroll
            for (int i = 0; i < 8; i++) CP16(dst + i * 16, src + i * 16);
            asm volatile("cp.async.commit_group;");
        }

        unsigned ksu = smbase + st * STAGE_BYTES;
        unsigned vsu = ksu + KBYTES;

        #pragma unroll
        for (int half = 0; half < 2; half++) {
            // ---- QK on 32 keys: S(log2 domain) ----
            float sf[2][4][4] = {};
            #pragma unroll
            for (int kk = 0; kk < 4; kk++) {
                unsigned base = ksu + (unsigned)((16 * kk + (lane & 15)) * 144)
                              + (unsigned)((lane >> 4) * 16) + half * 64u;
                #pragma unroll
                for (int npl = 0; npl < 2; npl++) {
                    unsigned r0, r1, r2, r3;
                    ldsm_x4_trans(r0, r1, r2, r3, base + npl * 32);
                    #pragma unroll
                    for (int mt = 0; mt < 2; mt++) {
                        mma_bf16(sf[mt][2 * npl],     qf[mt][kk], r0, r1);
                        mma_bf16(sf[mt][2 * npl + 1], qf[mt][kk], r2, r3);
                    }
                }
            }

            // ---- p = exp2(s): bf16x2 vector ex2, born-packed fragments ----
            unsigned pa[2][2][4];
            #pragma unroll
            for (int mt = 0; mt < 2; mt++) {
                #pragma unroll
                for (int nt = 0; nt < 4; nt++) {
                    int ks = nt >> 1, hi = (nt & 1) * 2;
                    pa[mt][ks][hi]     = ex2_bf16x2(pack_bf16(sf[mt][nt][0], sf[mt][nt][1]));
                    pa[mt][ks][hi + 1] = ex2_bf16x2(pack_bf16(sf[mt][nt][2], sf[mt][nt][3]));
                }
                mma_bf16(lacc[mt], pa[mt][0], ONES_BF16X2, ONES_BF16X2);
                mma_bf16(lacc[mt], pa[mt][1], ONES_BF16X2, ONES_BF16X2);
            }

            // ---- PV over this 32-key slice ----
            #pragma unroll
            for (int ks = 0; ks < 2; ks++) {
                int sc = 2 * half + ks;
                #pragma unroll
                for (int cp2 = 0; cp2 < 4; cp2++) {
                    int crow = cp2 * 16 + ((lane >> 4) << 3) + (lane & 7);
                    unsigned addr = vsu + (unsigned)(crow * 144)
                                  + (unsigned)(sc * 32 + ((lane >> 3) & 1) * 16);
                    unsigned r0, r1, r2, r3;
                    ldsm_x4(r0, r1, r2, r3, addr);
                    #pragma unroll
                    for (int mt = 0; mt < 2; mt++) {
                        mma_bf16(o[mt][2 * cp2],     pa[mt][ks], r0, r1);
                        mma_bf16(o[mt][2 * cp2 + 1], pa[mt][ks], r2, r3);
                    }
                }
            }
        }

        st = (st + 1 >= NSTAGE) ? 0 : st + 1;
    }

    // ---- epilogue: l already fully reduced by the ones-MMA ----
    __nv_bfloat16* hb = hout + (size_t)b * T * 256;
    #pragma unroll
    for (int mt = 0; mt < 2; mt++) {
        float i0 = 1.f / lacc[mt][0];
        float i1 = 1.f / lacc[mt][2];
        int tq = t0 + 32 * w + 16 * mt + qr;
        #pragma unroll
        for (int j = 0; j < 8; j++) {
            int c = hd * 64 + j * 8 + 2 * ql;
            *(unsigned*)&hb[(size_t)tq * 256 + c] =
                pack_bf16(o[mt][j][0] * i0, o[mt][j][1] * i0);
            *(unsigned*)&hb[(size_t)(tq + 8) * 256 + c] =
                pack_bf16(o[mt][j][2] * i1, o[mt][j][3] * i1);
        }
    }
}

// ---------------------------------------------------------------------------
// Launch
// ---------------------------------------------------------------------------
extern "C" void kernel_launch(void* const* d_in, const int* in_sizes, int n_in,
                              void* d_out, int out_size)
{
    const float* x      = (const float*)d_in[0];
    const float* norm_w = (const float*)d_in[1];
    const float* norm_b = (const float*)d_in[2];
    const float* qkv_w  = (const float*)d_in[3];
    const float* qkv_b  = (const float*)d_in[4];
    const float* proj_w = (const float*)d_in[5];
    const float* proj_b = (const float*)d_in[6];
    float* out = (float*)d_out;

    __nv_bfloat16 *normed_p, *qkv_p, *h_p, *wq_p, *wp_p;
    cudaGetSymbolAddress((void**)&normed_p, g_normed_t);
    cudaGetSymbolAddress((void**)&qkv_p,   g_qkv);
    cudaGetSymbolAddress((void**)&h_p,     g_ht);
    cudaGetSymbolAddress((void**)&wq_p,    g_wq);
    cudaGetSymbolAddress((void**)&wp_p,    g_wp);

    const int ATTN_SMEM = NSTAGE * STAGE_BYTES;   // 55296 B
    cudaFuncSetAttribute(attn_kernel, cudaFuncAttributeMaxDynamicSharedMemorySize,
                         ATTN_SMEM);
    cudaFuncSetAttribute(gemm_bf16, cudaFuncAttributeMaxDynamicSharedMemorySize,
                         GSM_TOTAL);              // 61440 B

    // 0+1a. Fused prep: GN partial sums + weight conversion
    prep_kernel<<<768, 256>>>(x, qkv_w, wq_p, proj_w, wp_p);

    // 1b. GroupNorm apply + transpose -> bf16 [b][t][c]
    gn_apply_t<<<dim3(T / 64, B), 128>>>(x, norm_w, norm_b, normed_p);

    // 2. QKV GEMM (128x128 tiles) -> [b][768][t] bf16, Q rows pre-scaled
    gemm_bf16<<<dim3(T / 128, 768 / 128, B), 256, GSM_TOTAL>>>(
        wq_p, normed_p, qkv_b, nullptr, qkv_p,
        (size_t)T * C, (size_t)768 * T, 0, 1);

    // 3. Flash attention -> h_t[b][t][c] bf16
    attn_kernel<<<dim3(T / BM, 16), 128, ATTN_SMEM>>>(qkv_p, h_p);

    // 4. Proj GEMM (128x128 tiles) + bias + residual -> d_out fp32 [b][c][t]
    gemm_bf16<<<dim3(T / 128, 256 / 128, B), 256, GSM_TOTAL>>>(
        wp_p, h_p, proj_b, x, out,
        (size_t)T * C, (size_t)C * T, (size_t)C * T, 0);
}